// round 2
// baseline (speedup 1.0000x reference)
#include <cuda_runtime.h>
#include <math.h>

// dims
#define BB   2
#define NNODE 256
#define DNv  128
#define DEv  64
#define DHv  128
#define Hh   8
#define DHHv 16
#define DNHv 512
#define DEHv 256
#define NLAYER 2
#define ATT_SCALE 0.088388347648318447f  // 1/sqrt(128)

// ---------------- scratch (device globals; no allocations allowed) ----------
__device__ float g_x[BB*NNODE*DNv];
__device__ float g_e[BB*NNODE*NNODE*DEv];
__device__ float g_e2[BB*NNODE*NNODE*DEv];
__device__ float g_qkvn[BB*NNODE*3*DHv];
__device__ float g_attnout[BB*NNODE*DHv];
__device__ float g_src[BB*NNODE*DEHv];
__device__ float g_tgt[BB*NNODE*DEHv];

__device__ __forceinline__ float gelu_f(float x) {
    return 0.5f * x * (1.0f + erff(x * 0.70710678118654752440f));
}

// ---------------- copy in ----------------------------------------------------
__global__ void k_copy_in(const float* __restrict__ node, const float* __restrict__ edge) {
    int tid = blockIdx.x * blockDim.x + threadIdx.x;
    int nt = gridDim.x * blockDim.x;
    for (int i = tid; i < BB*NNODE*DNv; i += nt) g_x[i] = node[i];
    for (int i = tid; i < BB*NNODE*NNODE*DEv; i += nt) g_e[i] = edge[i];
}

// ---------------- qkv_n: x @ Wqkv_n[l]  (rows of 384) ------------------------
__global__ void k_qkvn(const float* __restrict__ W) {  // W: [128][384]
    __shared__ float sx[DNv];
    int row = blockIdx.x;  // b*N+n
    int t = threadIdx.x;   // 128 threads
    sx[t] = g_x[row*DNv + t];
    __syncthreads();
    for (int c = t; c < 3*DHv; c += 128) {
        float acc = 0.f;
        #pragma unroll 8
        for (int k = 0; k < DNv; k++) acc += sx[k] * __ldg(&W[k*384 + c]);
        g_qkvn[row*384 + c] = acc;
    }
}

// ---------------- fused attention: per (b,i), flash-style over j -------------
// smem layout (floats): sE[32*513], seT[64*36], skn[32*129], svn[32*129], sq[128]
#define SMEM_ATTN ((32*513 + 64*36 + 32*129 + 32*129 + 128) * 4)
__global__ void k_attn(const float* __restrict__ We, int flip) {
    extern __shared__ float sm[];
    float* sE  = sm;                  // E tile row-major, stride 513 (bank-safe)
    float* seT = sE  + 32*513;        // e tile transposed [k=64][jj], stride 36
    float* skn = seT + 64*36;         // kn tile [jj][128], stride 129
    float* svn = skn + 32*129;        // vn tile
    float* sq  = svn + 32*129;        // q row (128)

    const float* eread = flip ? g_e2 : g_e;

    int b = blockIdx.x / NNODE, i = blockIdx.x % NNODE;
    int t = threadIdx.x, warp = t >> 5, lane = t & 31;
    int h = warp;  // 8 warps = 8 heads

    if (t < DHv) { int hh = t >> 4, d = t & 15; sq[t] = g_qkvn[(b*NNODE + i)*384 + hh*48 + d]; }

    float m = -3.4e38f, lsum = 0.f, o = 0.f;  // o owned by lanes<16 (d=lane)
    const float* erow = eread + (size_t)(b*NNODE + i) * NNODE * DEv;

    for (int j0 = 0; j0 < NNODE; j0 += 32) {
        __syncthreads();  // protect smem reuse from previous tile
        // load e tile transposed
        for (int idx = t; idx < 32*64; idx += 256) {
            int jj = idx >> 6, c = idx & 63;
            seT[c*36 + jj] = erow[(j0 + jj)*DEv + c];
        }
        // load kn, vn tiles
        for (int idx = t; idx < 32*128; idx += 256) {
            int jj = idx >> 7, c = idx & 127;
            int hh = c >> 4, d = c & 15;
            int base = (b*NNODE + j0 + jj)*384 + hh*48;
            skn[jj*129 + c] = g_qkvn[base + 16 + d];
            svn[jj*129 + c] = g_qkvn[base + 32 + d];
        }
        __syncthreads();
        // E = e_tile @ Wqkv_e  (32 x 512), register-blocked over 32 j rows
        for (int half = 0; half < 2; half++) {
            int c = half*256 + t;
            float acc[32];
            #pragma unroll
            for (int jj = 0; jj < 32; jj++) acc[jj] = 0.f;
            #pragma unroll 4
            for (int k = 0; k < 64; k++) {
                float w = __ldg(&We[k*512 + c]);
                const float4* e4 = (const float4*)(seT + k*36);
                #pragma unroll
                for (int q4 = 0; q4 < 8; q4++) {
                    float4 ev = e4[q4];
                    acc[q4*4+0] += ev.x * w;
                    acc[q4*4+1] += ev.y * w;
                    acc[q4*4+2] += ev.z * w;
                    acc[q4*4+3] += ev.w * w;
                }
            }
            #pragma unroll
            for (int jj = 0; jj < 32; jj++) sE[jj*513 + c] = acc[jj];
        }
        __syncthreads();
        // dots (lane = j within tile), online softmax per warp/head
        const float* Er = sE + lane*513 + h*64;
        const float* kr = skn + lane*129 + h*16;
        float dot = 0.f;
        #pragma unroll
        for (int d = 0; d < 16; d++)
            dot += (sq[h*16 + d] + Er[d]) * (kr[d] + Er[16 + d]);
        dot *= ATT_SCALE;
        float mt = dot;
        #pragma unroll
        for (int off = 16; off; off >>= 1) mt = fmaxf(mt, __shfl_xor_sync(0xffffffffu, mt, off));
        float mnew = fmaxf(m, mt);
        float p = expf(dot - mnew);
        float corr = expf(m - mnew);   // first tile: exp(-huge) = 0
        float ps = p;
        #pragma unroll
        for (int off = 16; off; off >>= 1) ps += __shfl_xor_sync(0xffffffffu, ps, off);
        lsum = lsum * corr + ps;
        o *= corr;
        // o[d] += sum_j p_j * (vn[j,d]*em[j,d] + ev[j,d])
        for (int jj = 0; jj < 32; jj++) {
            float pj = __shfl_sync(0xffffffffu, p, jj);
            if (lane < 16) {
                const float* Ej = sE + jj*513 + h*64;
                float v = svn[jj*129 + h*16 + lane] * Ej[48 + lane] + Ej[32 + lane];
                o += pj * v;
            }
        }
        m = mnew;
    }
    if (lane < 16)
        g_attnout[(b*NNODE + i)*DHv + h*16 + lane] = o / lsum;
}

// ---------------- LayerNorm helper for 128-wide rows (128 threads) -----------
__device__ __forceinline__ float ln128(float r, const float* __restrict__ g,
                                       const float* __restrict__ bta, float* sred, int t) {
    __syncthreads();  // protect sred reuse
    int warp = t >> 5, lane = t & 31;
    float s = r, ss = r*r;
    #pragma unroll
    for (int off = 16; off; off >>= 1) {
        s  += __shfl_xor_sync(0xffffffffu, s, off);
        ss += __shfl_xor_sync(0xffffffffu, ss, off);
    }
    if (lane == 0) { sred[warp] = s; sred[4 + warp] = ss; }
    __syncthreads();
    if (t == 0) {
        float S = sred[0]+sred[1]+sred[2]+sred[3];
        float SS = sred[4]+sred[5]+sred[6]+sred[7];
        float mean = S * (1.f/128.f);
        float var = SS * (1.f/128.f) - mean*mean;
        sred[8] = mean;
        sred[9] = rsqrtf(var + 1e-5f);
    }
    __syncthreads();
    return (r - sred[8]) * sred[9] * g[t] + bta[t];
}

// ---------------- node update 1: x = ln(x + (attn@Wo+bo)@Wl0 + bl0) ----------
__global__ void k_node1(const float* __restrict__ Wo, const float* __restrict__ bo,
                        const float* __restrict__ Wl0, const float* __restrict__ bl0,
                        const float* __restrict__ gam, const float* __restrict__ bet) {
    __shared__ float sa[DHv];
    __shared__ float st[DNv];
    __shared__ float sred[10];
    int row = blockIdx.x; int t = threadIdx.x;
    sa[t] = g_attnout[row*DHv + t];
    __syncthreads();
    float acc = bo[t];
    #pragma unroll 8
    for (int k = 0; k < DHv; k++) acc += sa[k] * __ldg(&Wo[k*DNv + t]);
    st[t] = acc;
    __syncthreads();
    float u = bl0[t];
    #pragma unroll 8
    for (int k = 0; k < DNv; k++) u += st[k] * __ldg(&Wl0[k*DNv + t]);
    float r = g_x[row*DNv + t] + u;
    g_x[row*DNv + t] = ln128(r, gam, bet, sred, t);
}

// ---------------- node MLP: x = ln(x + gelu(x@Wm1)@Wm2 + bm2) ----------------
__global__ void k_node2(const float* __restrict__ Wm1, const float* __restrict__ Wm2,
                        const float* __restrict__ bm2,
                        const float* __restrict__ gam, const float* __restrict__ bet) {
    __shared__ float sx[DNv];
    __shared__ float sh[DNHv];
    __shared__ float sred[10];
    int row = blockIdx.x; int t = threadIdx.x;
    float xv = g_x[row*DNv + t];
    sx[t] = xv;
    __syncthreads();
    for (int c = t; c < DNHv; c += 128) {
        float acc = 0.f;
        #pragma unroll 8
        for (int k = 0; k < DNv; k++) acc += sx[k] * __ldg(&Wm1[k*DNHv + c]);
        sh[c] = gelu_f(acc);
    }
    __syncthreads();
    float u = bm2[t];
    #pragma unroll 8
    for (int k = 0; k < DNHv; k++) u += sh[k] * __ldg(&Wm2[k*DNv + t]);
    float r = xv + u;
    g_x[row*DNv + t] = ln128(r, gam, bet, sred, t);
}

// ---------------- src/tgt projections (x@Ws+bs, x@Wt+bt) ---------------------
__global__ void k_srctgt(const float* __restrict__ Ws, const float* __restrict__ bs,
                         const float* __restrict__ Wt, const float* __restrict__ bt) {
    __shared__ float sx[DNv];
    int row = blockIdx.x; int t = threadIdx.x;  // 256 threads
    if (t < DNv) sx[t] = g_x[row*DNv + t];
    __syncthreads();
    float a = bs[t], c2 = bt[t];
    #pragma unroll 4
    for (int k = 0; k < DNv; k++) {
        float xv = sx[k];
        a  += xv * __ldg(&Ws[k*DEHv + t]);
        c2 += xv * __ldg(&Wt[k*DEHv + t]);
    }
    g_src[row*DEHv + t] = a;
    g_tgt[row*DEHv + t] = c2;
}

// ---------------- fused edge update kernel -----------------------------------
// block = (b, i, j-tile of 32), 256 threads
// smem (floats): secatT[128*36], shT[256*36], stRM[32*64], stT[64*36], r2[32*64], ssrc[256]
#define SMEM_EDGE ((128*36 + 256*36 + 2048 + 64*36 + 2048 + 256) * 4)
__global__ void k_edge(const float* __restrict__ We0, const float* __restrict__ be0,
                       const float* __restrict__ We1, const float* __restrict__ be1,
                       const float* __restrict__ g0, const float* __restrict__ b0,
                       const float* __restrict__ Wem1, const float* __restrict__ Wem2,
                       const float* __restrict__ bem2,
                       const float* __restrict__ g1, const float* __restrict__ b1,
                       int flip) {
    extern __shared__ float sm[];
    float* secatT = sm;                 // [k=128][jj=32] stride 36
    float* shT    = secatT + 128*36;    // [k=256][jj=32] stride 36
    float* stRM   = shT + 256*36;       // [jj=32][c=64] row-major
    float* stT    = stRM + 2048;        // [k=64][jj=32] stride 36
    float* r2     = stT + 64*36;        // [jj=32][c=64] row-major
    float* ssrc   = r2 + 2048;          // 256

    const float* eread = flip ? g_e2 : g_e;
    float* ewrite = flip ? g_e : g_e2;

    int jt = blockIdx.x & 7;
    int bi = blockIdx.x >> 3;           // b*N+i
    int b = bi >> 8, i = bi & 255;
    int j0 = jt * 32;
    int t = threadIdx.x;

    // load ecat = [e_ij, e_ji] transposed
    for (int idx = t; idx < 32*64; idx += 256) {
        int jj = idx >> 6, c = idx & 63;
        secatT[c*36 + jj]        = eread[((size_t)bi*NNODE + j0 + jj)*DEv + c];
        secatT[(64 + c)*36 + jj] = eread[((size_t)(b*NNODE + j0 + jj)*NNODE + i)*DEv + c];
    }
    ssrc[t] = g_src[(size_t)bi*DEHv + t];
    __syncthreads();

    // h = gelu(ecat @ We0 + be0 + src_i + tgt_j)   (32 x 256)
    {
        int c = t;
        float acc[32];
        float init = __ldg(&be0[c]) + ssrc[c];
        #pragma unroll
        for (int jj = 0; jj < 32; jj++) acc[jj] = init;
        #pragma unroll 2
        for (int k = 0; k < 128; k++) {
            float w = __ldg(&We0[k*DEHv + c]);
            const float4* e4 = (const float4*)(secatT + k*36);
            #pragma unroll
            for (int q4 = 0; q4 < 8; q4++) {
                float4 ev = e4[q4];
                acc[q4*4+0] += ev.x * w; acc[q4*4+1] += ev.y * w;
                acc[q4*4+2] += ev.z * w; acc[q4*4+3] += ev.w * w;
            }
        }
        #pragma unroll
        for (int jj = 0; jj < 32; jj++) {
            float v = acc[jj] + __ldg(&g_tgt[(size_t)(b*NNODE + j0 + jj)*DEHv + c]);
            shT[c*36 + jj] = gelu_f(v);
        }
    }
    __syncthreads();

    // e_pre = e + h @ We1 + be1     (32 x 64)
    {
        int c = t & 63, jg = t >> 6;
        float acc[8];
        #pragma unroll
        for (int n = 0; n < 8; n++) acc[n] = 0.f;
        #pragma unroll 2
        for (int k = 0; k < 256; k++) {
            float w = __ldg(&We1[k*64 + c]);
            const float4* h4 = (const float4*)(shT + k*36 + jg*8);
            float4 a0 = h4[0], a1 = h4[1];
            acc[0] += a0.x*w; acc[1] += a0.y*w; acc[2] += a0.z*w; acc[3] += a0.w*w;
            acc[4] += a1.x*w; acc[5] += a1.y*w; acc[6] += a1.z*w; acc[7] += a1.w*w;
        }
        float bb1 = __ldg(&be1[c]);
        #pragma unroll
        for (int n = 0; n < 8; n++) {
            int jj = jg*8 + n;
            stRM[jj*64 + c] = acc[n] + bb1 + eread[((size_t)bi*NNODE + j0 + jj)*DEv + c];
        }
    }
    __syncthreads();

    // LN0 per 64-wide row -> stRM (normalized) and stT (transposed)
    {
        int warp = t >> 5, lane = t & 31;
        for (int r = warp; r < 32; r += 8) {
            float a = stRM[r*64 + lane], q = stRM[r*64 + 32 + lane];
            float s = a + q, ss = a*a + q*q;
            #pragma unroll
            for (int off = 16; off; off >>= 1) {
                s  += __shfl_xor_sync(0xffffffffu, s, off);
                ss += __shfl_xor_sync(0xffffffffu, ss, off);
            }
            float mean = s * (1.f/64.f);
            float var = ss * (1.f/64.f) - mean*mean;
            float rstd = rsqrtf(var + 1e-5f);
            float y0 = (a - mean)*rstd*__ldg(&g0[lane])      + __ldg(&b0[lane]);
            float y1 = (q - mean)*rstd*__ldg(&g0[lane + 32]) + __ldg(&b0[lane + 32]);
            stRM[r*64 + lane] = y0; stRM[r*64 + 32 + lane] = y1;
            stT[lane*36 + r] = y0; stT[(lane + 32)*36 + r] = y1;
        }
    }
    __syncthreads();

    // hidden2 = gelu(e_new @ Wem1)   (32 x 256), reuse shT
    {
        int c = t;
        float acc[32];
        #pragma unroll
        for (int jj = 0; jj < 32; jj++) acc[jj] = 0.f;
        #pragma unroll 2
        for (int k = 0; k < 64; k++) {
            float w = __ldg(&Wem1[k*DEHv + c]);
            const float4* e4 = (const float4*)(stT + k*36);
            #pragma unroll
            for (int q4 = 0; q4 < 8; q4++) {
                float4 ev = e4[q4];
                acc[q4*4+0] += ev.x * w; acc[q4*4+1] += ev.y * w;
                acc[q4*4+2] += ev.z * w; acc[q4*4+3] += ev.w * w;
            }
        }
        #pragma unroll
        for (int jj = 0; jj < 32; jj++) shT[c*36 + jj] = gelu_f(acc[jj]);
    }
    __syncthreads();

    // r2 = e_new + hidden2 @ Wem2 + bem2   (32 x 64)
    {
        int c = t & 63, jg = t >> 6;
        float acc[8];
        #pragma unroll
        for (int n = 0; n < 8; n++) acc[n] = 0.f;
        #pragma unroll 2
        for (int k = 0; k < 256; k++) {
            float w = __ldg(&Wem2[k*64 + c]);
            const float4* h4 = (const float4*)(shT + k*36 + jg*8);
            float4 a0 = h4[0], a1 = h4[1];
            acc[0] += a0.x*w; acc[1] += a0.y*w; acc[2] += a0.z*w; acc[3] += a0.w*w;
            acc[4] += a1.x*w; acc[5] += a1.y*w; acc[6] += a1.z*w; acc[7] += a1.w*w;
        }
        float bb2 = __ldg(&bem2[c]);
        #pragma unroll
        for (int n = 0; n < 8; n++) {
            int jj = jg*8 + n;
            r2[jj*64 + c] = acc[n] + bb2 + stRM[jj*64 + c];
        }
    }
    __syncthreads();

    // LN1 per row -> write out
    {
        int warp = t >> 5, lane = t & 31;
        for (int r = warp; r < 32; r += 8) {
            float a = r2[r*64 + lane], q = r2[r*64 + 32 + lane];
            float s = a + q, ss = a*a + q*q;
            #pragma unroll
            for (int off = 16; off; off >>= 1) {
                s  += __shfl_xor_sync(0xffffffffu, s, off);
                ss += __shfl_xor_sync(0xffffffffu, ss, off);
            }
            float mean = s * (1.f/64.f);
            float var = ss * (1.f/64.f) - mean*mean;
            float rstd = rsqrtf(var + 1e-5f);
            float y0 = (a - mean)*rstd*__ldg(&g1[lane])      + __ldg(&b1[lane]);
            float y1 = (q - mean)*rstd*__ldg(&g1[lane + 32]) + __ldg(&b1[lane + 32]);
            size_t orow = ((size_t)bi*NNODE + j0 + r)*DEv;
            ewrite[orow + lane] = y0;
            ewrite[orow + 32 + lane] = y1;
        }
    }
}

// ---------------- copy out: [x (65536) | e (8388608)] ------------------------
__global__ void k_copy_out(float* __restrict__ out, int flip) {
    const float* efin = flip ? g_e2 : g_e;
    int tid = blockIdx.x * blockDim.x + threadIdx.x;
    int nt = gridDim.x * blockDim.x;
    for (int i = tid; i < BB*NNODE*DNv; i += nt) out[i] = g_x[i];
    for (int i = tid; i < BB*NNODE*NNODE*DEv; i += nt) out[BB*NNODE*DNv + i] = efin[i];
}

// ---------------- host launcher ----------------------------------------------
extern "C" void kernel_launch(void* const* d_in, const int* in_sizes, int n_in,
                              void* d_out, int out_size) {
    const float* node   = (const float*)d_in[0];
    const float* edge   = (const float*)d_in[1];
    const float* Wqkv_n = (const float*)d_in[2];
    const float* Wqkv_e = (const float*)d_in[3];
    const float* Wo     = (const float*)d_in[4];
    const float* bo     = (const float*)d_in[5];
    const float* Wl0    = (const float*)d_in[6];
    const float* bl0    = (const float*)d_in[7];
    const float* ln0_g  = (const float*)d_in[8];
    const float* ln0_b  = (const float*)d_in[9];
    const float* Wm1    = (const float*)d_in[10];
    const float* Wm2    = (const float*)d_in[11];
    const float* bm2    = (const float*)d_in[12];
    const float* ln1_g  = (const float*)d_in[13];
    const float* ln1_b  = (const float*)d_in[14];
    const float* We0    = (const float*)d_in[15];
    const float* be0    = (const float*)d_in[16];
    const float* Ws     = (const float*)d_in[17];
    const float* bs     = (const float*)d_in[18];
    const float* Wt     = (const float*)d_in[19];
    const float* bt     = (const float*)d_in[20];
    const float* We1    = (const float*)d_in[21];
    const float* be1    = (const float*)d_in[22];
    const float* eln0_g = (const float*)d_in[23];
    const float* eln0_b = (const float*)d_in[24];
    const float* Wem1   = (const float*)d_in[25];
    const float* Wem2   = (const float*)d_in[26];
    const float* bem2   = (const float*)d_in[27];
    const float* eln1_g = (const float*)d_in[28];
    const float* eln1_b = (const float*)d_in[29];
    float* out = (float*)d_out;

    cudaFuncSetAttribute(k_attn, cudaFuncAttributeMaxDynamicSharedMemorySize, SMEM_ATTN);
    cudaFuncSetAttribute(k_edge, cudaFuncAttributeMaxDynamicSharedMemorySize, SMEM_EDGE);

    k_copy_in<<<2048, 256>>>(node, edge);

    for (int l = 0; l < NLAYER; l++) {
        int flip = l & 1;  // 0: read g_e write g_e2 ; 1: read g_e2 write g_e
        k_qkvn<<<BB*NNODE, 128>>>(Wqkv_n + (size_t)l*DNv*3*DHv);
        k_attn<<<BB*NNODE, 256, SMEM_ATTN>>>(Wqkv_e + (size_t)l*DEv*4*DHv, flip);
        k_node1<<<BB*NNODE, 128>>>(Wo + (size_t)l*DHv*DNv, bo + l*DNv,
                                   Wl0 + (size_t)l*DNv*DNv, bl0 + l*DNv,
                                   ln0_g + l*DNv, ln0_b + l*DNv);
        k_node2<<<BB*NNODE, 128>>>(Wm1 + (size_t)l*DNv*DNHv, Wm2 + (size_t)l*DNHv*DNv,
                                   bm2 + l*DNv, ln1_g + l*DNv, ln1_b + l*DNv);
        k_srctgt<<<BB*NNODE, 256>>>(Ws + (size_t)l*DNv*DEHv, bs + l*DEHv,
                                    Wt + (size_t)l*DNv*DEHv, bt + l*DEHv);
        k_edge<<<BB*NNODE*8, 256, SMEM_EDGE>>>(
            We0 + (size_t)l*2*DEv*DEHv, be0 + l*DEHv,
            We1 + (size_t)l*DEHv*DEv,  be1 + l*DEv,
            eln0_g + l*DEv, eln0_b + l*DEv,
            Wem1 + (size_t)l*DEv*DEHv, Wem2 + (size_t)l*DEHv*DEv,
            bem2 + l*DEv, eln1_g + l*DEv, eln1_b + l*DEv, flip);
    }

    // after L=2 layers the final e is in g_e (flip=0 selects g_e)
    k_copy_out<<<2048, 256>>>(out, 0);
}

// round 3
// speedup vs baseline: 1.3990x; 1.3990x over previous
#include <cuda_runtime.h>
#include <math.h>

// dims
#define BB   2
#define NNODE 256
#define DNv  128
#define DEv  64
#define DHv  128
#define Hh   8
#define DHHv 16
#define DNHv 512
#define DEHv 256
#define NLAYER 2
#define ATT_SCALE 0.088388347648318447f  // 1/sqrt(128)

typedef unsigned long long u64t;

// packed fp32x2 FMA (Blackwell): one issue slot, two fp32 FMAs, exact .rn numerics
__device__ __forceinline__ void ffma2(u64t& acc, u64t a, u64t b) {
    asm("fma.rn.f32x2 %0, %1, %2, %0;" : "+l"(acc) : "l"(a), "l"(b));
}
__device__ __forceinline__ u64t pack_ww(float w) {
    u64t r; asm("mov.b64 %0, {%1, %1};" : "=l"(r) : "f"(w)); return r;
}
union F4u { float4 v; u64t p[2]; };
union U2u { u64t p; float f[2]; };

// ---------------- scratch (device globals; no allocations allowed) ----------
__device__ float g_x[BB*NNODE*DNv];
__device__ float g_e[BB*NNODE*NNODE*DEv];
__device__ float g_e2[BB*NNODE*NNODE*DEv];
__device__ float g_qkvn[BB*NNODE*3*DHv];
__device__ float g_attnout[BB*NNODE*DHv];
__device__ float g_src[BB*NNODE*DEHv];
__device__ float g_tgt[BB*NNODE*DEHv];

__device__ __forceinline__ float gelu_f(float x) {
    return 0.5f * x * (1.0f + erff(x * 0.70710678118654752440f));
}

// ---------------- copy in ----------------------------------------------------
__global__ void k_copy_in(const float* __restrict__ node, const float* __restrict__ edge) {
    int tid = blockIdx.x * blockDim.x + threadIdx.x;
    int nt = gridDim.x * blockDim.x;
    for (int i = tid; i < BB*NNODE*DNv; i += nt) g_x[i] = node[i];
    for (int i = tid; i < BB*NNODE*NNODE*DEv; i += nt) g_e[i] = edge[i];
}

// ---------------- qkv_n: x @ Wqkv_n[l]  (rows of 384) ------------------------
__global__ void k_qkvn(const float* __restrict__ W) {  // W: [128][384]
    __shared__ float sx[DNv];
    int row = blockIdx.x;  // b*N+n
    int t = threadIdx.x;   // 128 threads
    sx[t] = g_x[row*DNv + t];
    __syncthreads();
    for (int c = t; c < 3*DHv; c += 128) {
        float acc = 0.f;
        #pragma unroll 16
        for (int k = 0; k < DNv; k++) acc += sx[k] * __ldg(&W[k*384 + c]);
        g_qkvn[row*384 + c] = acc;
    }
}

// ---------------- fused attention: per (b,i), flash-style over j -------------
// smem layout (floats): sE[32*513], seT[64*36], skn[32*129], svn[32*129], sq[128]
#define SMEM_ATTN ((32*513 + 64*36 + 32*129 + 32*129 + 128) * 4)
__global__ void __launch_bounds__(256, 2) k_attn(const float* __restrict__ We, int flip) {
    extern __shared__ float sm[];
    float* sE  = sm;                  // E tile row-major, stride 513 (bank-safe)
    float* seT = sE  + 32*513;        // e tile transposed [k=64][jj], stride 36
    float* skn = seT + 64*36;         // kn tile [jj][128], stride 129
    float* svn = skn + 32*129;        // vn tile
    float* sq  = svn + 32*129;        // q row (128)

    const float* eread = flip ? g_e2 : g_e;

    int b = blockIdx.x / NNODE, i = blockIdx.x % NNODE;
    int t = threadIdx.x, warp = t >> 5, lane = t & 31;
    int h = warp;  // 8 warps = 8 heads

    if (t < DHv) { int hh = t >> 4, d = t & 15; sq[t] = g_qkvn[(b*NNODE + i)*384 + hh*48 + d]; }

    float m = -3.4e38f, lsum = 0.f, o = 0.f;  // o owned by lanes<16 (d=lane)
    const float* erow = eread + (size_t)(b*NNODE + i) * NNODE * DEv;

    for (int j0 = 0; j0 < NNODE; j0 += 32) {
        __syncthreads();  // protect smem reuse from previous tile
        // load e tile transposed
        for (int idx = t; idx < 32*64; idx += 256) {
            int jj = idx >> 6, c = idx & 63;
            seT[c*36 + jj] = erow[(j0 + jj)*DEv + c];
        }
        // load kn, vn tiles
        for (int idx = t; idx < 32*128; idx += 256) {
            int jj = idx >> 7, c = idx & 127;
            int hh = c >> 4, d = c & 15;
            int base = (b*NNODE + j0 + jj)*384 + hh*48;
            skn[jj*129 + c] = g_qkvn[base + 16 + d];
            svn[jj*129 + c] = g_qkvn[base + 32 + d];
        }
        __syncthreads();
        // E = e_tile @ Wqkv_e  (32 x 512), f32x2 register-blocked over 32 j rows
        for (int half = 0; half < 2; half++) {
            int c = half*256 + t;
            u64t acc[16];
            #pragma unroll
            for (int q = 0; q < 16; q++) acc[q] = 0ull;
            #pragma unroll 4
            for (int k = 0; k < 64; k++) {
                u64t ww = pack_ww(__ldg(&We[k*512 + c]));
                const float4* e4 = (const float4*)(seT + k*36);
                #pragma unroll
                for (int q4 = 0; q4 < 8; q4++) {
                    F4u ev; ev.v = e4[q4];
                    ffma2(acc[q4*2],   ev.p[0], ww);
                    ffma2(acc[q4*2+1], ev.p[1], ww);
                }
            }
            #pragma unroll
            for (int q = 0; q < 16; q++) {
                U2u u; u.p = acc[q];
                sE[(2*q)*513 + c]   = u.f[0];
                sE[(2*q+1)*513 + c] = u.f[1];
            }
        }
        __syncthreads();
        // dots (lane = j within tile), online softmax per warp/head
        const float* Er = sE + lane*513 + h*64;
        const float* kr = skn + lane*129 + h*16;
        float dot = 0.f;
        #pragma unroll
        for (int d = 0; d < 16; d++)
            dot += (sq[h*16 + d] + Er[d]) * (kr[d] + Er[16 + d]);
        dot *= ATT_SCALE;
        float mt = dot;
        #pragma unroll
        for (int off = 16; off; off >>= 1) mt = fmaxf(mt, __shfl_xor_sync(0xffffffffu, mt, off));
        float mnew = fmaxf(m, mt);
        float p = expf(dot - mnew);
        float corr = expf(m - mnew);   // first tile: exp(-huge) = 0
        float ps = p;
        #pragma unroll
        for (int off = 16; off; off >>= 1) ps += __shfl_xor_sync(0xffffffffu, ps, off);
        lsum = lsum * corr + ps;
        o *= corr;
        // o[d] += sum_j p_j * (vn[j,d]*em[j,d] + ev[j,d])
        for (int jj = 0; jj < 32; jj++) {
            float pj = __shfl_sync(0xffffffffu, p, jj);
            if (lane < 16) {
                const float* Ej = sE + jj*513 + h*64;
                float v = svn[jj*129 + h*16 + lane] * Ej[48 + lane] + Ej[32 + lane];
                o += pj * v;
            }
        }
        m = mnew;
    }
    if (lane < 16)
        g_attnout[(b*NNODE + i)*DHv + h*16 + lane] = o / lsum;
}

// ---------------- LayerNorm helper for 128-wide rows (128 threads) -----------
__device__ __forceinline__ float ln128(float r, const float* __restrict__ g,
                                       const float* __restrict__ bta, float* sred, int t) {
    __syncthreads();  // protect sred reuse
    int warp = t >> 5, lane = t & 31;
    float s = r, ss = r*r;
    #pragma unroll
    for (int off = 16; off; off >>= 1) {
        s  += __shfl_xor_sync(0xffffffffu, s, off);
        ss += __shfl_xor_sync(0xffffffffu, ss, off);
    }
    if (lane == 0) { sred[warp] = s; sred[4 + warp] = ss; }
    __syncthreads();
    if (t == 0) {
        float S = sred[0]+sred[1]+sred[2]+sred[3];
        float SS = sred[4]+sred[5]+sred[6]+sred[7];
        float mean = S * (1.f/128.f);
        float var = SS * (1.f/128.f) - mean*mean;
        sred[8] = mean;
        sred[9] = rsqrtf(var + 1e-5f);
    }
    __syncthreads();
    return (r - sred[8]) * sred[9] * g[t] + bta[t];
}

// ---------------- node update 1: x = ln(x + (attn@Wo+bo)@Wl0 + bl0) ----------
__global__ void k_node1(const float* __restrict__ Wo, const float* __restrict__ bo,
                        const float* __restrict__ Wl0, const float* __restrict__ bl0,
                        const float* __restrict__ gam, const float* __restrict__ bet) {
    __shared__ float sa[DHv];
    __shared__ float st[DNv];
    __shared__ float sred[10];
    int row = blockIdx.x; int t = threadIdx.x;
    sa[t] = g_attnout[row*DHv + t];
    __syncthreads();
    float acc = bo[t];
    #pragma unroll 16
    for (int k = 0; k < DHv; k++) acc += sa[k] * __ldg(&Wo[k*DNv + t]);
    st[t] = acc;
    __syncthreads();
    float u = bl0[t];
    #pragma unroll 16
    for (int k = 0; k < DNv; k++) u += st[k] * __ldg(&Wl0[k*DNv + t]);
    float r = g_x[row*DNv + t] + u;
    g_x[row*DNv + t] = ln128(r, gam, bet, sred, t);
}

// ---------------- node MLP: x = ln(x + gelu(x@Wm1)@Wm2 + bm2) ----------------
__global__ void k_node2(const float* __restrict__ Wm1, const float* __restrict__ Wm2,
                        const float* __restrict__ bm2,
                        const float* __restrict__ gam, const float* __restrict__ bet) {
    __shared__ float sx[DNv];
    __shared__ float sh[DNHv];
    __shared__ float sred[10];
    int row = blockIdx.x; int t = threadIdx.x;
    float xv = g_x[row*DNv + t];
    sx[t] = xv;
    __syncthreads();
    for (int c = t; c < DNHv; c += 128) {
        float acc = 0.f;
        #pragma unroll 16
        for (int k = 0; k < DNv; k++) acc += sx[k] * __ldg(&Wm1[k*DNHv + c]);
        sh[c] = gelu_f(acc);
    }
    __syncthreads();
    float u = bm2[t];
    #pragma unroll 16
    for (int k = 0; k < DNHv; k++) u += sh[k] * __ldg(&Wm2[k*DNv + t]);
    float r = xv + u;
    g_x[row*DNv + t] = ln128(r, gam, bet, sred, t);
}

// ---------------- src/tgt projections (x@Ws+bs, x@Wt+bt) ---------------------
__global__ void k_srctgt(const float* __restrict__ Ws, const float* __restrict__ bs,
                         const float* __restrict__ Wt, const float* __restrict__ bt) {
    __shared__ float sx[DNv];
    int row = blockIdx.x; int t = threadIdx.x;  // 256 threads
    if (t < DNv) sx[t] = g_x[row*DNv + t];
    __syncthreads();
    float a = bs[t], c2 = bt[t];
    #pragma unroll 16
    for (int k = 0; k < DNv; k++) {
        float xv = sx[k];
        a  += xv * __ldg(&Ws[k*DEHv + t]);
        c2 += xv * __ldg(&Wt[k*DEHv + t]);
    }
    g_src[row*DEHv + t] = a;
    g_tgt[row*DEHv + t] = c2;
}

// ---------------- fused edge update kernel -----------------------------------
// block = (b, i, j-tile of 32), 256 threads
// smem (floats): secatT[128*36], shT[256*36], stRM[32*64], stT[64*36], r2[32*64], ssrc[256]
#define SMEM_EDGE ((128*36 + 256*36 + 2048 + 64*36 + 2048 + 256) * 4)
__global__ void __launch_bounds__(256, 2) k_edge(
                       const float* __restrict__ We0, const float* __restrict__ be0,
                       const float* __restrict__ We1, const float* __restrict__ be1,
                       const float* __restrict__ g0, const float* __restrict__ b0,
                       const float* __restrict__ Wem1, const float* __restrict__ Wem2,
                       const float* __restrict__ bem2,
                       const float* __restrict__ g1, const float* __restrict__ b1,
                       int flip) {
    extern __shared__ float sm[];
    float* secatT = sm;                 // [k=128][jj=32] stride 36
    float* shT    = secatT + 128*36;    // [k=256][jj=32] stride 36
    float* stRM   = shT + 256*36;       // [jj=32][c=64] row-major
    float* stT    = stRM + 2048;        // [k=64][jj=32] stride 36
    float* r2     = stT + 64*36;        // [jj=32][c=64] row-major
    float* ssrc   = r2 + 2048;          // 256

    const float* eread = flip ? g_e2 : g_e;
    float* ewrite = flip ? g_e : g_e2;

    int jt = blockIdx.x & 7;
    int bi = blockIdx.x >> 3;           // b*N+i
    int b = bi >> 8, i = bi & 255;
    int j0 = jt * 32;
    int t = threadIdx.x;

    // load ecat = [e_ij, e_ji] transposed
    for (int idx = t; idx < 32*64; idx += 256) {
        int jj = idx >> 6, c = idx & 63;
        secatT[c*36 + jj]        = eread[((size_t)bi*NNODE + j0 + jj)*DEv + c];
        secatT[(64 + c)*36 + jj] = eread[((size_t)(b*NNODE + j0 + jj)*NNODE + i)*DEv + c];
    }
    ssrc[t] = g_src[(size_t)bi*DEHv + t];
    __syncthreads();

    // h = gelu(ecat @ We0 + be0 + src_i + tgt_j)   (32 x 256)
    {
        int c = t;
        u64t acc[16];
        u64t init = pack_ww(__ldg(&be0[c]) + ssrc[c]);
        #pragma unroll
        for (int q = 0; q < 16; q++) acc[q] = init;
        #pragma unroll 4
        for (int k = 0; k < 128; k++) {
            u64t ww = pack_ww(__ldg(&We0[k*DEHv + c]));
            const float4* e4 = (const float4*)(secatT + k*36);
            #pragma unroll
            for (int q4 = 0; q4 < 8; q4++) {
                F4u ev; ev.v = e4[q4];
                ffma2(acc[q4*2],   ev.p[0], ww);
                ffma2(acc[q4*2+1], ev.p[1], ww);
            }
        }
        #pragma unroll
        for (int q = 0; q < 16; q++) {
            U2u u; u.p = acc[q];
            int jj = 2*q;
            float v0 = u.f[0] + __ldg(&g_tgt[(size_t)(b*NNODE + j0 + jj)*DEHv + c]);
            float v1 = u.f[1] + __ldg(&g_tgt[(size_t)(b*NNODE + j0 + jj + 1)*DEHv + c]);
            shT[c*36 + jj]     = gelu_f(v0);
            shT[c*36 + jj + 1] = gelu_f(v1);
        }
    }
    __syncthreads();

    // e_pre = e + h @ We1 + be1     (32 x 64)
    {
        int c = t & 63, jg = t >> 6;
        u64t acc[4];
        #pragma unroll
        for (int n = 0; n < 4; n++) acc[n] = 0ull;
        #pragma unroll 8
        for (int k = 0; k < 256; k++) {
            u64t ww = pack_ww(__ldg(&We1[k*64 + c]));
            const float4* h4 = (const float4*)(shT + k*36 + jg*8);
            F4u a0, a1; a0.v = h4[0]; a1.v = h4[1];
            ffma2(acc[0], a0.p[0], ww); ffma2(acc[1], a0.p[1], ww);
            ffma2(acc[2], a1.p[0], ww); ffma2(acc[3], a1.p[1], ww);
        }
        float bb1 = __ldg(&be1[c]);
        #pragma unroll
        for (int n = 0; n < 4; n++) {
            U2u u; u.p = acc[n];
            int jj = jg*8 + 2*n;
            stRM[jj*64 + c]     = u.f[0] + bb1 + eread[((size_t)bi*NNODE + j0 + jj)*DEv + c];
            stRM[(jj+1)*64 + c] = u.f[1] + bb1 + eread[((size_t)bi*NNODE + j0 + jj + 1)*DEv + c];
        }
    }
    __syncthreads();

    // LN0 per 64-wide row -> stRM (normalized) and stT (transposed)
    {
        int warp = t >> 5, lane = t & 31;
        for (int r = warp; r < 32; r += 8) {
            float a = stRM[r*64 + lane], q = stRM[r*64 + 32 + lane];
            float s = a + q, ss = a*a + q*q;
            #pragma unroll
            for (int off = 16; off; off >>= 1) {
                s  += __shfl_xor_sync(0xffffffffu, s, off);
                ss += __shfl_xor_sync(0xffffffffu, ss, off);
            }
            float mean = s * (1.f/64.f);
            float var = ss * (1.f/64.f) - mean*mean;
            float rstd = rsqrtf(var + 1e-5f);
            float y0 = (a - mean)*rstd*__ldg(&g0[lane])      + __ldg(&b0[lane]);
            float y1 = (q - mean)*rstd*__ldg(&g0[lane + 32]) + __ldg(&b0[lane + 32]);
            stRM[r*64 + lane] = y0; stRM[r*64 + 32 + lane] = y1;
            stT[lane*36 + r] = y0; stT[(lane + 32)*36 + r] = y1;
        }
    }
    __syncthreads();

    // hidden2 = gelu(e_new @ Wem1)   (32 x 256), reuse shT
    {
        int c = t;
        u64t acc[16];
        #pragma unroll
        for (int q = 0; q < 16; q++) acc[q] = 0ull;
        #pragma unroll 4
        for (int k = 0; k < 64; k++) {
            u64t ww = pack_ww(__ldg(&Wem1[k*DEHv + c]));
            const float4* e4 = (const float4*)(stT + k*36);
            #pragma unroll
            for (int q4 = 0; q4 < 8; q4++) {
                F4u ev; ev.v = e4[q4];
                ffma2(acc[q4*2],   ev.p[0], ww);
                ffma2(acc[q4*2+1], ev.p[1], ww);
            }
        }
        #pragma unroll
        for (int q = 0; q < 16; q++) {
            U2u u; u.p = acc[q];
            shT[c*36 + 2*q]     = gelu_f(u.f[0]);
            shT[c*36 + 2*q + 1] = gelu_f(u.f[1]);
        }
    }
    __syncthreads();

    // r2 = e_new + hidden2 @ Wem2 + bem2   (32 x 64)
    {
        int c = t & 63, jg = t >> 6;
        u64t acc[4];
        #pragma unroll
        for (int n = 0; n < 4; n++) acc[n] = 0ull;
        #pragma unroll 8
        for (int k = 0; k < 256; k++) {
            u64t ww = pack_ww(__ldg(&Wem2[k*64 + c]));
            const float4* h4 = (const float4*)(shT + k*36 + jg*8);
            F4u a0, a1; a0.v = h4[0]; a1.v = h4[1];
            ffma2(acc[0], a0.p[0], ww); ffma2(acc[1], a0.p[1], ww);
            ffma2(acc[2], a1.p[0], ww); ffma2(acc[3], a1.p[1], ww);
        }
        float bb2 = __ldg(&bem2[c]);
        #pragma unroll
        for (int n = 0; n < 4; n++) {
            U2u u; u.p = acc[n];
            int jj = jg*8 + 2*n;
            r2[jj*64 + c]     = u.f[0] + bb2 + stRM[jj*64 + c];
            r2[(jj+1)*64 + c] = u.f[1] + bb2 + stRM[(jj+1)*64 + c];
        }
    }
    __syncthreads();

    // LN1 per row -> write out
    {
        int warp = t >> 5, lane = t & 31;
        for (int r = warp; r < 32; r += 8) {
            float a = r2[r*64 + lane], q = r2[r*64 + 32 + lane];
            float s = a + q, ss = a*a + q*q;
            #pragma unroll
            for (int off = 16; off; off >>= 1) {
                s  += __shfl_xor_sync(0xffffffffu, s, off);
                ss += __shfl_xor_sync(0xffffffffu, ss, off);
            }
            float mean = s * (1.f/64.f);
            float var = ss * (1.f/64.f) - mean*mean;
            float rstd = rsqrtf(var + 1e-5f);
            float y0 = (a - mean)*rstd*__ldg(&g1[lane])      + __ldg(&b1[lane]);
            float y1 = (q - mean)*rstd*__ldg(&g1[lane + 32]) + __ldg(&b1[lane + 32]);
            size_t orow = ((size_t)bi*NNODE + j0 + r)*DEv;
            ewrite[orow + lane] = y0;
            ewrite[orow + 32 + lane] = y1;
        }
    }
}

// ---------------- copy out: [x (65536) | e (8388608)] ------------------------
__global__ void k_copy_out(float* __restrict__ out, int flip) {
    const float* efin = flip ? g_e2 : g_e;
    int tid = blockIdx.x * blockDim.x + threadIdx.x;
    int nt = gridDim.x * blockDim.x;
    for (int i = tid; i < BB*NNODE*DNv; i += nt) out[i] = g_x[i];
    for (int i = tid; i < BB*NNODE*NNODE*DEv; i += nt) out[BB*NNODE*DNv + i] = efin[i];
}

// ---------------- host launcher ----------------------------------------------
extern "C" void kernel_launch(void* const* d_in, const int* in_sizes, int n_in,
                              void* d_out, int out_size) {
    const float* node   = (const float*)d_in[0];
    const float* edge   = (const float*)d_in[1];
    const float* Wqkv_n = (const float*)d_in[2];
    const float* Wqkv_e = (const float*)d_in[3];
    const float* Wo     = (const float*)d_in[4];
    const float* bo     = (const float*)d_in[5];
    const float* Wl0    = (const float*)d_in[6];
    const float* bl0    = (const float*)d_in[7];
    const float* ln0_g  = (const float*)d_in[8];
    const float* ln0_b  = (const float*)d_in[9];
    const float* Wm1    = (const float*)d_in[10];
    const float* Wm2    = (const float*)d_in[11];
    const float* bm2    = (const float*)d_in[12];
    const float* ln1_g  = (const float*)d_in[13];
    const float* ln1_b  = (const float*)d_in[14];
    const float* We0    = (const float*)d_in[15];
    const float* be0    = (const float*)d_in[16];
    const float* Ws     = (const float*)d_in[17];
    const float* bs     = (const float*)d_in[18];
    const float* Wt     = (const float*)d_in[19];
    const float* bt     = (const float*)d_in[20];
    const float* We1    = (const float*)d_in[21];
    const float* be1    = (const float*)d_in[22];
    const float* eln0_g = (const float*)d_in[23];
    const float* eln0_b = (const float*)d_in[24];
    const float* Wem1   = (const float*)d_in[25];
    const float* Wem2   = (const float*)d_in[26];
    const float* bem2   = (const float*)d_in[27];
    const float* eln1_g = (const float*)d_in[28];
    const float* eln1_b = (const float*)d_in[29];
    float* out = (float*)d_out;

    cudaFuncSetAttribute(k_attn, cudaFuncAttributeMaxDynamicSharedMemorySize, SMEM_ATTN);
    cudaFuncSetAttribute(k_edge, cudaFuncAttributeMaxDynamicSharedMemorySize, SMEM_EDGE);

    k_copy_in<<<2048, 256>>>(node, edge);

    for (int l = 0; l < NLAYER; l++) {
        int flip = l & 1;  // 0: read g_e write g_e2 ; 1: read g_e2 write g_e
        k_qkvn<<<BB*NNODE, 128>>>(Wqkv_n + (size_t)l*DNv*3*DHv);
        k_attn<<<BB*NNODE, 256, SMEM_ATTN>>>(Wqkv_e + (size_t)l*DEv*4*DHv, flip);
        k_node1<<<BB*NNODE, 128>>>(Wo + (size_t)l*DHv*DNv, bo + l*DNv,
                                   Wl0 + (size_t)l*DNv*DNv, bl0 + l*DNv,
                                   ln0_g + l*DNv, ln0_b + l*DNv);
        k_node2<<<BB*NNODE, 128>>>(Wm1 + (size_t)l*DNv*DNHv, Wm2 + (size_t)l*DNHv*DNv,
                                   bm2 + l*DNv, ln1_g + l*DNv, ln1_b + l*DNv);
        k_srctgt<<<BB*NNODE, 256>>>(Ws + (size_t)l*DNv*DEHv, bs + l*DEHv,
                                    Wt + (size_t)l*DNv*DEHv, bt + l*DEHv);
        k_edge<<<BB*NNODE*8, 256, SMEM_EDGE>>>(
            We0 + (size_t)l*2*DEv*DEHv, be0 + l*DEHv,
            We1 + (size_t)l*DEHv*DEv,  be1 + l*DEv,
            eln0_g + l*DEv, eln0_b + l*DEv,
            Wem1 + (size_t)l*DEv*DEHv, Wem2 + (size_t)l*DEHv*DEv,
            bem2 + l*DEv, eln1_g + l*DEv, eln1_b + l*DEv, flip);
    }

    // after L=2 layers the final e is in g_e (flip=0 selects g_e)
    k_copy_out<<<2048, 256>>>(out, 0);
}

// round 4
// speedup vs baseline: 1.6527x; 1.1813x over previous
#include <cuda_runtime.h>
#include <math.h>

// dims
#define BB   2
#define NNODE 256
#define DNv  128
#define DEv  64
#define DHv  128
#define Hh   8
#define DHHv 16
#define DNHv 512
#define DEHv 256
#define NLAYER 2
#define ATT_SCALE 0.088388347648318447f  // 1/sqrt(128)

typedef unsigned long long u64t;

// packed fp32x2 FMA (Blackwell): one issue slot, two fp32 FMAs, exact .rn numerics
__device__ __forceinline__ void ffma2(u64t& acc, u64t a, u64t b) {
    asm("fma.rn.f32x2 %0, %1, %2, %0;" : "+l"(acc) : "l"(a), "l"(b));
}
__device__ __forceinline__ u64t pack_ww(float w) {
    u64t r; asm("mov.b64 %0, {%1, %1};" : "=l"(r) : "f"(w)); return r;
}
union F4u { float4 v; u64t p[2]; };
union U2u { u64t p; float f[2]; };

// ---------------- scratch (device globals; no allocations allowed) ----------
__device__ float g_x[BB*NNODE*DNv];
__device__ float g_e[BB*NNODE*NNODE*DEv];
__device__ float g_e2[BB*NNODE*NNODE*DEv];
__device__ float g_qkvn[BB*NNODE*3*DHv];
__device__ float g_attnout[BB*NNODE*DHv];
__device__ float g_src[BB*NNODE*DEHv];
__device__ float g_tgt[BB*NNODE*DEHv];

__device__ __forceinline__ float gelu_f(float x) {
    return 0.5f * x * (1.0f + erff(x * 0.70710678118654752440f));
}

// ---------------- copy in ----------------------------------------------------
__global__ void k_copy_in(const float* __restrict__ node, const float* __restrict__ edge) {
    int tid = blockIdx.x * blockDim.x + threadIdx.x;
    int nt = gridDim.x * blockDim.x;
    for (int i = tid; i < BB*NNODE*DNv; i += nt) g_x[i] = node[i];
    for (int i = tid; i < BB*NNODE*NNODE*DEv; i += nt) g_e[i] = edge[i];
}

// ---------------- qkv_n: x @ Wqkv_n[l]  (rows of 384) ------------------------
__global__ void k_qkvn(const float* __restrict__ W) {  // W: [128][384]
    __shared__ float sx[DNv];
    int row = blockIdx.x;  // b*N+n
    int t = threadIdx.x;   // 128 threads
    sx[t] = g_x[row*DNv + t];
    __syncthreads();
    for (int c = t; c < 3*DHv; c += 128) {
        float acc = 0.f;
        #pragma unroll 16
        for (int k = 0; k < DNv; k++) acc += sx[k] * __ldg(&W[k*384 + c]);
        g_qkvn[row*384 + c] = acc;
    }
}

// ---------------- fused attention: per (b,i), flash-style over j -------------
// smem layout (floats): sE[32*513], seT[64*36], skn[32*129], svn[32*129], sq[128]
#define SMEM_ATTN ((32*513 + 64*36 + 32*129 + 32*129 + 128) * 4)
__global__ void __launch_bounds__(256, 2) k_attn(const float* __restrict__ We, int flip) {
    extern __shared__ float sm[];
    float* sE  = sm;                  // E tile row-major, stride 513 (bank-safe)
    float* seT = sE  + 32*513;        // e tile transposed [k=64][jj], stride 36
    float* skn = seT + 64*36;         // kn tile [jj][128], stride 129
    float* svn = skn + 32*129;        // vn tile
    float* sq  = svn + 32*129;        // q row (128)

    const float* eread = flip ? g_e2 : g_e;

    int b = blockIdx.x / NNODE, i = blockIdx.x % NNODE;
    int t = threadIdx.x, warp = t >> 5, lane = t & 31;
    int h = warp;  // 8 warps = 8 heads
    int dd = lane & 15, hi = lane >> 4;  // AV split: lane half 'hi' owns j-rows hi*16..

    if (t < DHv) { int hh = t >> 4, d = t & 15; sq[t] = g_qkvn[(b*NNODE + i)*384 + hh*48 + d]; }

    float m = -3.4e38f, lsum = 0.f, o = 0.f;  // o: partial over this lane-half's j
    const float* erow = eread + (size_t)(b*NNODE + i) * NNODE * DEv;

    for (int j0 = 0; j0 < NNODE; j0 += 32) {
        __syncthreads();  // protect smem reuse from previous tile
        // load e tile transposed
        for (int idx = t; idx < 32*64; idx += 256) {
            int jj = idx >> 6, c = idx & 63;
            seT[c*36 + jj] = erow[(j0 + jj)*DEv + c];
        }
        // load kn, vn tiles
        for (int idx = t; idx < 32*128; idx += 256) {
            int jj = idx >> 7, c = idx & 127;
            int hh = c >> 4, d = c & 15;
            int base = (b*NNODE + j0 + jj)*384 + hh*48;
            skn[jj*129 + c] = g_qkvn[base + 16 + d];
            svn[jj*129 + c] = g_qkvn[base + 32 + d];
        }
        __syncthreads();
        // E = e_tile @ Wqkv_e  (32 x 512), f32x2, C=2 column-blocked (c, c+256)
        {
            int c0 = t;
            u64t acc[32];
            #pragma unroll
            for (int q = 0; q < 32; q++) acc[q] = 0ull;
            #pragma unroll 4
            for (int k = 0; k < 64; k++) {
                u64t w0 = pack_ww(__ldg(&We[k*512 + c0]));
                u64t w1 = pack_ww(__ldg(&We[k*512 + c0 + 256]));
                const float4* e4 = (const float4*)(seT + k*36);
                #pragma unroll
                for (int q4 = 0; q4 < 8; q4++) {
                    F4u ev; ev.v = e4[q4];
                    ffma2(acc[q4*2],        ev.p[0], w0);
                    ffma2(acc[q4*2+1],      ev.p[1], w0);
                    ffma2(acc[16 + q4*2],   ev.p[0], w1);
                    ffma2(acc[16 + q4*2+1], ev.p[1], w1);
                }
            }
            #pragma unroll
            for (int q = 0; q < 16; q++) {
                U2u u; u.p = acc[q];
                sE[(2*q)*513 + c0]   = u.f[0];
                sE[(2*q+1)*513 + c0] = u.f[1];
                U2u v; v.p = acc[16 + q];
                sE[(2*q)*513 + c0 + 256]   = v.f[0];
                sE[(2*q+1)*513 + c0 + 256] = v.f[1];
            }
        }
        __syncthreads();
        // dots (lane = j within tile), online softmax per warp/head
        const float* Er = sE + lane*513 + h*64;
        const float* kr = skn + lane*129 + h*16;
        float dot = 0.f;
        #pragma unroll
        for (int d = 0; d < 16; d++)
            dot += (sq[h*16 + d] + Er[d]) * (kr[d] + Er[16 + d]);
        dot *= ATT_SCALE;
        float mt = dot;
        #pragma unroll
        for (int off = 16; off; off >>= 1) mt = fmaxf(mt, __shfl_xor_sync(0xffffffffu, mt, off));
        float mnew = fmaxf(m, mt);
        float p = expf(dot - mnew);
        float corr = expf(m - mnew);   // first tile: exp(-huge) = 0
        float ps = p;
        #pragma unroll
        for (int off = 16; off; off >>= 1) ps += __shfl_xor_sync(0xffffffffu, ps, off);
        lsum = lsum * corr + ps;
        o *= corr;
        // o[d] += sum_j p_j * (vn[j,d]*em[j,d] + ev[j,d]) — full warp, j split by lane-half
        #pragma unroll
        for (int jj = 0; jj < 16; jj++) {
            int jjj = hi*16 + jj;
            float pj = __shfl_sync(0xffffffffu, p, jjj);
            const float* Ej = sE + jjj*513 + h*64;
            float v = svn[jjj*129 + h*16 + dd] * Ej[48 + dd] + Ej[32 + dd];
            o += pj * v;
        }
        m = mnew;
    }
    // combine the two j-halves
    float of = o + __shfl_xor_sync(0xffffffffu, o, 16);
    if (lane < 16)
        g_attnout[(b*NNODE + i)*DHv + h*16 + lane] = of / lsum;
}

// ---------------- LayerNorm helper for 128-wide rows (128 threads) -----------
__device__ __forceinline__ float ln128(float r, const float* __restrict__ g,
                                       const float* __restrict__ bta, float* sred, int t) {
    __syncthreads();  // protect sred reuse
    int warp = t >> 5, lane = t & 31;
    float s = r, ss = r*r;
    #pragma unroll
    for (int off = 16; off; off >>= 1) {
        s  += __shfl_xor_sync(0xffffffffu, s, off);
        ss += __shfl_xor_sync(0xffffffffu, ss, off);
    }
    if (lane == 0) { sred[warp] = s; sred[4 + warp] = ss; }
    __syncthreads();
    if (t == 0) {
        float S = sred[0]+sred[1]+sred[2]+sred[3];
        float SS = sred[4]+sred[5]+sred[6]+sred[7];
        float mean = S * (1.f/128.f);
        float var = SS * (1.f/128.f) - mean*mean;
        sred[8] = mean;
        sred[9] = rsqrtf(var + 1e-5f);
    }
    __syncthreads();
    return (r - sred[8]) * sred[9] * g[t] + bta[t];
}

// ---------------- node update 1: x = ln(x + (attn@Wo+bo)@Wl0 + bl0) ----------
__global__ void k_node1(const float* __restrict__ Wo, const float* __restrict__ bo,
                        const float* __restrict__ Wl0, const float* __restrict__ bl0,
                        const float* __restrict__ gam, const float* __restrict__ bet) {
    __shared__ float sa[DHv];
    __shared__ float st[DNv];
    __shared__ float sred[10];
    int row = blockIdx.x; int t = threadIdx.x;
    sa[t] = g_attnout[row*DHv + t];
    __syncthreads();
    float acc = bo[t];
    #pragma unroll 16
    for (int k = 0; k < DHv; k++) acc += sa[k] * __ldg(&Wo[k*DNv + t]);
    st[t] = acc;
    __syncthreads();
    float u = bl0[t];
    #pragma unroll 16
    for (int k = 0; k < DNv; k++) u += st[k] * __ldg(&Wl0[k*DNv + t]);
    float r = g_x[row*DNv + t] + u;
    g_x[row*DNv + t] = ln128(r, gam, bet, sred, t);
}

// ---------------- node MLP: x = ln(x + gelu(x@Wm1)@Wm2 + bm2) ----------------
__global__ void k_node2(const float* __restrict__ Wm1, const float* __restrict__ Wm2,
                        const float* __restrict__ bm2,
                        const float* __restrict__ gam, const float* __restrict__ bet) {
    __shared__ float sx[DNv];
    __shared__ float sh[DNHv];
    __shared__ float sred[10];
    int row = blockIdx.x; int t = threadIdx.x;
    float xv = g_x[row*DNv + t];
    sx[t] = xv;
    __syncthreads();
    for (int c = t; c < DNHv; c += 128) {
        float acc = 0.f;
        #pragma unroll 16
        for (int k = 0; k < DNv; k++) acc += sx[k] * __ldg(&Wm1[k*DNHv + c]);
        sh[c] = gelu_f(acc);
    }
    __syncthreads();
    float u = bm2[t];
    #pragma unroll 16
    for (int k = 0; k < DNHv; k++) u += sh[k] * __ldg(&Wm2[k*DNv + t]);
    float r = xv + u;
    g_x[row*DNv + t] = ln128(r, gam, bet, sred, t);
}

// ---------------- src/tgt projections (x@Ws+bs, x@Wt+bt) ---------------------
__global__ void k_srctgt(const float* __restrict__ Ws, const float* __restrict__ bs,
                         const float* __restrict__ Wt, const float* __restrict__ bt) {
    __shared__ float sx[DNv];
    int row = blockIdx.x; int t = threadIdx.x;  // 256 threads
    if (t < DNv) sx[t] = g_x[row*DNv + t];
    __syncthreads();
    float a = bs[t], c2 = bt[t];
    #pragma unroll 16
    for (int k = 0; k < DNv; k++) {
        float xv = sx[k];
        a  += xv * __ldg(&Ws[k*DEHv + t]);
        c2 += xv * __ldg(&Wt[k*DEHv + t]);
    }
    g_src[row*DEHv + t] = a;
    g_tgt[row*DEHv + t] = c2;
}

// ---------------- fused edge update kernel -----------------------------------
// block = (b, i, j-tile of 32), 256 threads
// smem (floats): secatT[128*36], shT[256*36], stRM[32*64], stT[64*36], r2[32*64], ssrc[256]
#define SMEM_EDGE ((128*36 + 256*36 + 2048 + 64*36 + 2048 + 256) * 4)
__global__ void __launch_bounds__(256, 2) k_edge(
                       const float* __restrict__ We0, const float* __restrict__ be0,
                       const float* __restrict__ We1, const float* __restrict__ be1,
                       const float* __restrict__ g0, const float* __restrict__ b0,
                       const float* __restrict__ Wem1, const float* __restrict__ Wem2,
                       const float* __restrict__ bem2,
                       const float* __restrict__ g1, const float* __restrict__ b1,
                       int flip) {
    extern __shared__ float sm[];
    float* secatT = sm;                 // [k=128][jj=32] stride 36
    float* shT    = secatT + 128*36;    // [k=256][jj=32] stride 36
    float* stRM   = shT + 256*36;       // [jj=32][c=64] row-major
    float* stT    = stRM + 2048;        // [k=64][jj=32] stride 36
    float* r2     = stT + 64*36;        // [jj=32][c=64] row-major
    float* ssrc   = r2 + 2048;          // 256

    const float* eread = flip ? g_e2 : g_e;
    float* ewrite = flip ? g_e : g_e2;

    int jt = blockIdx.x & 7;
    int bi = blockIdx.x >> 3;           // b*N+i
    int b = bi >> 8, i = bi & 255;
    int j0 = jt * 32;
    int t = threadIdx.x;

    // load ecat = [e_ij, e_ji] transposed
    for (int idx = t; idx < 32*64; idx += 256) {
        int jj = idx >> 6, c = idx & 63;
        secatT[c*36 + jj]        = eread[((size_t)bi*NNODE + j0 + jj)*DEv + c];
        secatT[(64 + c)*36 + jj] = eread[((size_t)(b*NNODE + j0 + jj)*NNODE + i)*DEv + c];
    }
    ssrc[t] = g_src[(size_t)bi*DEHv + t];
    __syncthreads();

    // h = gelu(ecat @ We0 + be0 + src_i + tgt_j)   (32 x 256), C=2 cols x 16 rows
    {
        int c = t & 127;     // cols c and c+128
        int jg = t >> 7;     // row-half: rows jg*16 .. jg*16+15
        u64t acc0[8], acc1[8];
        u64t init0 = pack_ww(__ldg(&be0[c])       + ssrc[c]);
        u64t init1 = pack_ww(__ldg(&be0[c + 128]) + ssrc[c + 128]);
        #pragma unroll
        for (int q = 0; q < 8; q++) { acc0[q] = init0; acc1[q] = init1; }
        #pragma unroll 4
        for (int k = 0; k < 128; k++) {
            u64t w0 = pack_ww(__ldg(&We0[k*DEHv + c]));
            u64t w1 = pack_ww(__ldg(&We0[k*DEHv + c + 128]));
            const float4* e4 = (const float4*)(secatT + k*36 + jg*16);
            #pragma unroll
            for (int q4 = 0; q4 < 4; q4++) {
                F4u ev; ev.v = e4[q4];
                ffma2(acc0[q4*2],   ev.p[0], w0);
                ffma2(acc0[q4*2+1], ev.p[1], w0);
                ffma2(acc1[q4*2],   ev.p[0], w1);
                ffma2(acc1[q4*2+1], ev.p[1], w1);
            }
        }
        #pragma unroll
        for (int q = 0; q < 8; q++) {
            int jj = jg*16 + 2*q;
            size_t tb0 = (size_t)(b*NNODE + j0 + jj)*DEHv;
            size_t tb1 = (size_t)(b*NNODE + j0 + jj + 1)*DEHv;
            U2u u0; u0.p = acc0[q];
            shT[c*36 + jj]     = gelu_f(u0.f[0] + __ldg(&g_tgt[tb0 + c]));
            shT[c*36 + jj + 1] = gelu_f(u0.f[1] + __ldg(&g_tgt[tb1 + c]));
            U2u u1; u1.p = acc1[q];
            shT[(c+128)*36 + jj]     = gelu_f(u1.f[0] + __ldg(&g_tgt[tb0 + c + 128]));
            shT[(c+128)*36 + jj + 1] = gelu_f(u1.f[1] + __ldg(&g_tgt[tb1 + c + 128]));
        }
    }
    __syncthreads();

    // e_pre = e + h @ We1 + be1     (32 x 64)
    {
        int c = t & 63, jg = t >> 6;
        u64t acc[4];
        #pragma unroll
        for (int n = 0; n < 4; n++) acc[n] = 0ull;
        #pragma unroll 8
        for (int k = 0; k < 256; k++) {
            u64t ww = pack_ww(__ldg(&We1[k*64 + c]));
            const float4* h4 = (const float4*)(shT + k*36 + jg*8);
            F4u a0, a1; a0.v = h4[0]; a1.v = h4[1];
            ffma2(acc[0], a0.p[0], ww); ffma2(acc[1], a0.p[1], ww);
            ffma2(acc[2], a1.p[0], ww); ffma2(acc[3], a1.p[1], ww);
        }
        float bb1 = __ldg(&be1[c]);
        #pragma unroll
        for (int n = 0; n < 4; n++) {
            U2u u; u.p = acc[n];
            int jj = jg*8 + 2*n;
            stRM[jj*64 + c]     = u.f[0] + bb1 + eread[((size_t)bi*NNODE + j0 + jj)*DEv + c];
            stRM[(jj+1)*64 + c] = u.f[1] + bb1 + eread[((size_t)bi*NNODE + j0 + jj + 1)*DEv + c];
        }
    }
    __syncthreads();

    // LN0 per 64-wide row -> stRM (normalized) and stT (transposed)
    {
        int warp = t >> 5, lane = t & 31;
        for (int r = warp; r < 32; r += 8) {
            float a = stRM[r*64 + lane], q = stRM[r*64 + 32 + lane];
            float s = a + q, ss = a*a + q*q;
            #pragma unroll
            for (int off = 16; off; off >>= 1) {
                s  += __shfl_xor_sync(0xffffffffu, s, off);
                ss += __shfl_xor_sync(0xffffffffu, ss, off);
            }
            float mean = s * (1.f/64.f);
            float var = ss * (1.f/64.f) - mean*mean;
            float rstd = rsqrtf(var + 1e-5f);
            float y0 = (a - mean)*rstd*__ldg(&g0[lane])      + __ldg(&b0[lane]);
            float y1 = (q - mean)*rstd*__ldg(&g0[lane + 32]) + __ldg(&b0[lane + 32]);
            stRM[r*64 + lane] = y0; stRM[r*64 + 32 + lane] = y1;
            stT[lane*36 + r] = y0; stT[(lane + 32)*36 + r] = y1;
        }
    }
    __syncthreads();

    // hidden2 = gelu(e_new @ Wem1)   (32 x 256), reuse shT; C=2 cols x 16 rows
    {
        int c = t & 127;
        int jg = t >> 7;
        u64t acc0[8], acc1[8];
        #pragma unroll
        for (int q = 0; q < 8; q++) { acc0[q] = 0ull; acc1[q] = 0ull; }
        #pragma unroll 4
        for (int k = 0; k < 64; k++) {
            u64t w0 = pack_ww(__ldg(&Wem1[k*DEHv + c]));
            u64t w1 = pack_ww(__ldg(&Wem1[k*DEHv + c + 128]));
            const float4* e4 = (const float4*)(stT + k*36 + jg*16);
            #pragma unroll
            for (int q4 = 0; q4 < 4; q4++) {
                F4u ev; ev.v = e4[q4];
                ffma2(acc0[q4*2],   ev.p[0], w0);
                ffma2(acc0[q4*2+1], ev.p[1], w0);
                ffma2(acc1[q4*2],   ev.p[0], w1);
                ffma2(acc1[q4*2+1], ev.p[1], w1);
            }
        }
        #pragma unroll
        for (int q = 0; q < 8; q++) {
            int jj = jg*16 + 2*q;
            U2u u0; u0.p = acc0[q];
            shT[c*36 + jj]     = gelu_f(u0.f[0]);
            shT[c*36 + jj + 1] = gelu_f(u0.f[1]);
            U2u u1; u1.p = acc1[q];
            shT[(c+128)*36 + jj]     = gelu_f(u1.f[0]);
            shT[(c+128)*36 + jj + 1] = gelu_f(u1.f[1]);
        }
    }
    __syncthreads();

    // r2 = e_new + hidden2 @ Wem2 + bem2   (32 x 64)
    {
        int c = t & 63, jg = t >> 6;
        u64t acc[4];
        #pragma unroll
        for (int n = 0; n < 4; n++) acc[n] = 0ull;
        #pragma unroll 8
        for (int k = 0; k < 256; k++) {
            u64t ww = pack_ww(__ldg(&Wem2[k*64 + c]));
            const float4* h4 = (const float4*)(shT + k*36 + jg*8);
            F4u a0, a1; a0.v = h4[0]; a1.v = h4[1];
            ffma2(acc[0], a0.p[0], ww); ffma2(acc[1], a0.p[1], ww);
            ffma2(acc[2], a1.p[0], ww); ffma2(acc[3], a1.p[1], ww);
        }
        float bb2 = __ldg(&bem2[c]);
        #pragma unroll
        for (int n = 0; n < 4; n++) {
            U2u u; u.p = acc[n];
            int jj = jg*8 + 2*n;
            r2[jj*64 + c]     = u.f[0] + bb2 + stRM[jj*64 + c];
            r2[(jj+1)*64 + c] = u.f[1] + bb2 + stRM[(jj+1)*64 + c];
        }
    }
    __syncthreads();

    // LN1 per row -> write out
    {
        int warp = t >> 5, lane = t & 31;
        for (int r = warp; r < 32; r += 8) {
            float a = r2[r*64 + lane], q = r2[r*64 + 32 + lane];
            float s = a + q, ss = a*a + q*q;
            #pragma unroll
            for (int off = 16; off; off >>= 1) {
                s  += __shfl_xor_sync(0xffffffffu, s, off);
                ss += __shfl_xor_sync(0xffffffffu, ss, off);
            }
            float mean = s * (1.f/64.f);
            float var = ss * (1.f/64.f) - mean*mean;
            float rstd = rsqrtf(var + 1e-5f);
            float y0 = (a - mean)*rstd*__ldg(&g1[lane])      + __ldg(&b1[lane]);
            float y1 = (q - mean)*rstd*__ldg(&g1[lane + 32]) + __ldg(&b1[lane + 32]);
            size_t orow = ((size_t)bi*NNODE + j0 + r)*DEv;
            ewrite[orow + lane] = y0;
            ewrite[orow + 32 + lane] = y1;
        }
    }
}

// ---------------- copy out: [x (65536) | e (8388608)] ------------------------
__global__ void k_copy_out(float* __restrict__ out, int flip) {
    const float* efin = flip ? g_e2 : g_e;
    int tid = blockIdx.x * blockDim.x + threadIdx.x;
    int nt = gridDim.x * blockDim.x;
    for (int i = tid; i < BB*NNODE*DNv; i += nt) out[i] = g_x[i];
    for (int i = tid; i < BB*NNODE*NNODE*DEv; i += nt) out[BB*NNODE*DNv + i] = efin[i];
}

// ---------------- host launcher ----------------------------------------------
extern "C" void kernel_launch(void* const* d_in, const int* in_sizes, int n_in,
                              void* d_out, int out_size) {
    const float* node   = (const float*)d_in[0];
    const float* edge   = (const float*)d_in[1];
    const float* Wqkv_n = (const float*)d_in[2];
    const float* Wqkv_e = (const float*)d_in[3];
    const float* Wo     = (const float*)d_in[4];
    const float* bo     = (const float*)d_in[5];
    const float* Wl0    = (const float*)d_in[6];
    const float* bl0    = (const float*)d_in[7];
    const float* ln0_g  = (const float*)d_in[8];
    const float* ln0_b  = (const float*)d_in[9];
    const float* Wm1    = (const float*)d_in[10];
    const float* Wm2    = (const float*)d_in[11];
    const float* bm2    = (const float*)d_in[12];
    const float* ln1_g  = (const float*)d_in[13];
    const float* ln1_b  = (const float*)d_in[14];
    const float* We0    = (const float*)d_in[15];
    const float* be0    = (const float*)d_in[16];
    const float* Ws     = (const float*)d_in[17];
    const float* bs     = (const float*)d_in[18];
    const float* Wt     = (const float*)d_in[19];
    const float* bt     = (const float*)d_in[20];
    const float* We1    = (const float*)d_in[21];
    const float* be1    = (const float*)d_in[22];
    const float* eln0_g = (const float*)d_in[23];
    const float* eln0_b = (const float*)d_in[24];
    const float* Wem1   = (const float*)d_in[25];
    const float* Wem2   = (const float*)d_in[26];
    const float* bem2   = (const float*)d_in[27];
    const float* eln1_g = (const float*)d_in[28];
    const float* eln1_b = (const float*)d_in[29];
    float* out = (float*)d_out;

    cudaFuncSetAttribute(k_attn, cudaFuncAttributeMaxDynamicSharedMemorySize, SMEM_ATTN);
    cudaFuncSetAttribute(k_edge, cudaFuncAttributeMaxDynamicSharedMemorySize, SMEM_EDGE);

    k_copy_in<<<2048, 256>>>(node, edge);

    for (int l = 0; l < NLAYER; l++) {
        int flip = l & 1;  // 0: read g_e write g_e2 ; 1: read g_e2 write g_e
        k_qkvn<<<BB*NNODE, 128>>>(Wqkv_n + (size_t)l*DNv*3*DHv);
        k_attn<<<BB*NNODE, 256, SMEM_ATTN>>>(Wqkv_e + (size_t)l*DEv*4*DHv, flip);
        k_node1<<<BB*NNODE, 128>>>(Wo + (size_t)l*DHv*DNv, bo + l*DNv,
                                   Wl0 + (size_t)l*DNv*DNv, bl0 + l*DNv,
                                   ln0_g + l*DNv, ln0_b + l*DNv);
        k_node2<<<BB*NNODE, 128>>>(Wm1 + (size_t)l*DNv*DNHv, Wm2 + (size_t)l*DNHv*DNv,
                                   bm2 + l*DNv, ln1_g + l*DNv, ln1_b + l*DNv);
        k_srctgt<<<BB*NNODE, 256>>>(Ws + (size_t)l*DNv*DEHv, bs + l*DEHv,
                                    Wt + (size_t)l*DNv*DEHv, bt + l*DEHv);
        k_edge<<<BB*NNODE*8, 256, SMEM_EDGE>>>(
            We0 + (size_t)l*2*DEv*DEHv, be0 + l*DEHv,
            We1 + (size_t)l*DEHv*DEv,  be1 + l*DEv,
            eln0_g + l*DEv, eln0_b + l*DEv,
            Wem1 + (size_t)l*DEv*DEHv, Wem2 + (size_t)l*DEHv*DEv,
            bem2 + l*DEv, eln1_g + l*DEv, eln1_b + l*DEv, flip);
    }

    // after L=2 layers the final e is in g_e (flip=0 selects g_e)
    k_copy_out<<<2048, 256>>>(out, 0);
}